// round 17
// baseline (speedup 1.0000x reference)
#include <cuda_runtime.h>

// RNN_26895085207932 : Elman RNN, SEQ=2048, B=4096, IN=1, H=32 + Linear(32->1)
// R16: R12 champion (bit-identical math) + two orthogonal latency levers:
//  (1) CTA phase stagger (__nanosleep by bx&15) — breaks lockstep stalling of
//      the ~14 identical warps/SM so their shuffle/LDS stall windows interleave.
//  (2) Fully unrolled 32-step hot block with compile-time ring-row offsets —
//      LDS/STS become base+immediate (no per-step pointer arithmetic) and
//      ptxas gets a whole-block scheduling window.

typedef unsigned long long ull;

static constexpr int SEQ = 2048;
static constexpr int B   = 4096;
static constexpr int H   = 32;
static constexpr int ROWF2 = 34;             // ring row stride in float2 (2 pad)
static constexpr int ROWB  = ROWF2 * 8;      // 272 bytes; 16B-aligned rows

__device__ __forceinline__ ull pack2(float lo, float hi) {
    ull r; asm("mov.b64 %0, {%1, %2};" : "=l"(r) : "f"(lo), "f"(hi)); return r;
}
__device__ __forceinline__ void unpack2(ull v, float& lo, float& hi) {
    asm("mov.b64 {%0, %1}, %2;" : "=f"(lo), "=f"(hi) : "l"(v));
}
__device__ __forceinline__ ull fma2(ull a, ull b, ull c) {
    ull d; asm("fma.rn.f32x2 %0, %1, %2, %3;" : "=l"(d) : "l"(a), "l"(b), "l"(c)); return d;
}
__device__ __forceinline__ ull add2(ull a, ull b) {
    ull d; asm("add.rn.f32x2 %0, %1, %2;" : "=l"(d) : "l"(a), "l"(b)); return d;
}
__device__ __forceinline__ ull mul2(ull a, ull b) {
    ull d; asm("mul.rn.f32x2 %0, %1, %2;" : "=l"(d) : "l"(a), "l"(b)); return d;
}
__device__ __forceinline__ ull shfl_xor2(ull v, int d) {
    unsigned lo = (unsigned)v, hi = (unsigned)(v >> 32);
    lo = __shfl_xor_sync(0xffffffffu, lo, d);
    hi = __shfl_xor_sync(0xffffffffu, hi, d);
    return ((ull)hi << 32) | (ull)lo;
}
__device__ __forceinline__ float tanh_fast(float z) {
    float r; asm("tanh.approx.f32 %0, %1;" : "=f"(r) : "f"(z)); return r;
}
__device__ __forceinline__ void sts64(ull v, const void* p) {
    asm volatile("st.shared.b64 [%0], %1;"
                 :: "l"(__cvta_generic_to_shared(p)), "l"(v) : "memory");
}
__device__ __forceinline__ float guard_scale(float w) {
    float a = fabsf(w);
    return (a < 1e-6f) ? copysignf(1e-6f, w) : w;
}

// Shared step body given read/write addresses (math identical to R12).
#define STEP_BODY(XS, RD, WR)                                                 \
    {                                                                         \
        const ulonglong2* hq_ = (const ulonglong2*)(RD);                      \
        ull pA = fma2(pack2((XS).x, (XS).y), wih2, bias2);                    \
        ull pB = 0, pC = 0, pD = 0;                                           \
        _Pragma("unroll")                                                     \
        for (int kk = 0; kk < 4; kk++) {                                      \
            ulonglong2 hv = hq_[kk];                                          \
            pA = fma2(hv.x, wa[2 * kk],     pA);                              \
            pB = fma2(hv.x, wb[2 * kk],     pB);                              \
            pC = fma2(hv.x, wc[2 * kk],     pC);                              \
            pD = fma2(hv.x, wd[2 * kk],     pD);                              \
            pA = fma2(hv.y, wa[2 * kk + 1], pA);                              \
            pB = fma2(hv.y, wb[2 * kk + 1], pB);                              \
            pC = fma2(hv.y, wc[2 * kk + 1], pC);                              \
            pD = fma2(hv.y, wd[2 * kk + 1], pD);                              \
        }                                                                     \
        ull r1 = shfl_xor2(pB, 8);                                            \
        ull r2 = shfl_xor2(pC, 16);                                           \
        ull r3 = shfl_xor2(pD, 24);                                           \
        ull z  = add2(add2(pA, r1), add2(r2, r3));                            \
        float zA_, zB_;                                                       \
        unpack2(z, zA_, zB_);                                                 \
        const ull h2_ = pack2(tanh_fast(zA_), tanh_fast(zB_));                \
        sts64(mul2(h2_, sfc2), (WR));                                         \
    }

// Hot-block step, T = literal 0..31: ring rows are compile-time immediates.
#define STEP_I(T)                                                             \
    {                                                                         \
        float2 xs = xpipe[(T) & 3];                                           \
        xpipe[(T) & 3] = xnext[(size_t)(base + (T)) * (B / 2)];               \
        STEP_BODY(xs, rbase + (((T) + 31) & 31) * ROWB,                       \
                      wbase + ((T) & 31) * ROWB)                              \
    }

// Tail step (runtime row pointers, guarded x prefetch) — R12 form.
#define STEP_T(ST)                                                            \
    {                                                                         \
        const int st_ = (ST);                                                 \
        float2 xs = xpipe[st_ & 3];                                           \
        if (st_ + 4 < SEQ)                                                    \
            xpipe[st_ & 3] = xnext[(size_t)st_ * (B / 2)];                    \
        STEP_BODY(xs, rdq, wrp)                                               \
        rdq = wrp + dqs;                                                      \
        wrp += ROWB;                                                          \
    }

__global__ void __launch_bounds__(32, 14)
rnn_kernel(const float* __restrict__ x,      // (SEQ, B, 1)
           const float* __restrict__ hidden, // (1, B, H)
           const float* __restrict__ Wih,    // (H, 1)
           const float* __restrict__ bih,    // (H)
           const float* __restrict__ Whh,    // (H, H)
           const float* __restrict__ bhh,    // (H)
           const float* __restrict__ Wfc,    // (1, H)
           const float* __restrict__ bfc,    // (1)
           float* __restrict__ out)          // (SEQ, B, 1)
{
    __shared__ __align__(16) float2 ring[32][ROWF2];  // s*h per 32-step block

    const int j = threadIdx.x;
    const int q = j >> 3;                // k-quarter this lane reads
    const int g = j & 7;                 // quartet group
    const int myu = 4 * g + q;           // unit this lane owns
    const int ub  = 4 * g + (q ^ 1);     // unit of lane j^8
    const int uc  = 4 * g + (q ^ 2);     // unit of lane j^16
    const int ud  = 4 * g + (q ^ 3);     // unit of lane j^24
    const int kofs = 8 * q;

    const int bx = blockIdx.x;           // batch pair
    const int b0 = bx * 2;

    // De-phase CTAs sharing an SM: breaks lockstep stall alignment.
    __nanosleep((unsigned)((bx & 15) * 60));

    // Pre-divided weights: w'[u][k] = Whh[u][k] / s_k (s = guarded Wfc).
    ull wa[8], wb[8], wc[8], wd[8];
#pragma unroll
    for (int k = 0; k < 8; k++) {
        float inv = 1.0f / guard_scale(Wfc[kofs + k]);
        float a = Whh[myu * H + kofs + k] * inv;
        float b = Whh[ub  * H + kofs + k] * inv;
        float c = Whh[uc  * H + kofs + k] * inv;
        float d = Whh[ud  * H + kofs + k] * inv;
        wa[k] = pack2(a, a);
        wb[k] = pack2(b, b);
        wc[k] = pack2(c, c);
        wd[k] = pack2(d, d);
    }
    const float wih  = Wih[myu];
    const float bias = bih[myu] + bhh[myu];
    const ull wih2   = pack2(wih, wih);
    const ull bias2  = pack2(bias, bias);
    const float sfc  = guard_scale(Wfc[myu]);
    const ull sfc2   = pack2(sfc, sfc);
    const float bfc0 = bfc[0];

    // Initial state in row 31 (step 0 reads it).
    ring[31][myu] = make_float2(sfc * hidden[(size_t)b0 * H + myu],
                                sfc * hidden[(size_t)(b0 + 1) * H + myu]);
    __syncwarp();

    const float2* xg = reinterpret_cast<const float2*>(x) + bx;   // step stride B/2
    float2* og       = reinterpret_cast<float2*>(out) + bx;

    char* const ring0 = reinterpret_cast<char*>(&ring[0][0]);
    const char* const rbase = ring0 + 8 * kofs;   // my read-quarter base (row 0)
    char* const wbase       = ring0 + 8 * myu;    // my write slot (row 0)
    const int dqs = (8 * q - myu) * 8;            // tail: write slot -> read base
    const char* rdq;
    char* wrp;

    float2 xpipe[4];
#pragma unroll
    for (int i = 0; i < 4; i++) xpipe[i] = xg[(size_t)i * (B / 2)];
    const float2* xnext = xg + 4 * (size_t)(B / 2);

    for (int base = 0; base < SEQ; base += 32) {
        if (base + 32 < SEQ) {
            // Fully unrolled hot block: all ring offsets are immediates.
            STEP_I(0)  STEP_I(1)  STEP_I(2)  STEP_I(3)
            STEP_I(4)  STEP_I(5)  STEP_I(6)  STEP_I(7)
            STEP_I(8)  STEP_I(9)  STEP_I(10) STEP_I(11)
            STEP_I(12) STEP_I(13) STEP_I(14) STEP_I(15)
            STEP_I(16) STEP_I(17) STEP_I(18) STEP_I(19)
            STEP_I(20) STEP_I(21) STEP_I(22) STEP_I(23)
            STEP_I(24) STEP_I(25) STEP_I(26) STEP_I(27)
            STEP_I(28) STEP_I(29) STEP_I(30) STEP_I(31)
        } else {
            rdq = ring0 + 31 * ROWB + 8 * kofs;
            wrp = ring0 + 8 * myu;
#pragma unroll 1
            for (int qq = 0; qq < 8; qq++) {
                const int s4 = base + qq * 4;
                STEP_T(s4 + 0)
                STEP_T(s4 + 1)
                STEP_T(s4 + 2)
                STEP_T(s4 + 3)
            }
        }

        // Output reduction: lane j sums row j (timestep base+j), + bfc.
        {
            const ulonglong2* pr = reinterpret_cast<const ulonglong2*>(&ring[j][0]);
            ull s0 = 0, s1 = 0, s2 = 0, s3 = 0;
#pragma unroll
            for (int g2 = 0; g2 < 8; g2++) {
                ulonglong2 a = pr[2 * g2];
                ulonglong2 b = pr[2 * g2 + 1];
                s0 = add2(s0, a.x); s1 = add2(s1, a.y);
                s2 = add2(s2, b.x); s3 = add2(s3, b.y);
            }
            ull sv = add2(add2(s0, s1), add2(s2, s3));
            float oA, oB;
            unpack2(sv, oA, oB);
            og[(size_t)(base + j) * (B / 2)] = make_float2(oA + bfc0, oB + bfc0);
        }
    }
}

extern "C" void kernel_launch(void* const* d_in, const int* in_sizes, int n_in,
                              void* d_out, int out_size) {
    const float* x      = (const float*)d_in[0];
    const float* hidden = (const float*)d_in[1];
    const float* Wih    = (const float*)d_in[2];
    const float* bih    = (const float*)d_in[3];
    const float* Whh    = (const float*)d_in[4];
    const float* bhh    = (const float*)d_in[5];
    const float* Wfc    = (const float*)d_in[6];
    const float* bfc    = (const float*)d_in[7];
    (void)in_sizes; (void)n_in; (void)out_size;

    rnn_kernel<<<B / 2, 32>>>(x, hidden, Wih, bih, Whh, bhh, Wfc, bfc, (float*)d_out);
}